// round 1
// baseline (speedup 1.0000x reference)
#include <cuda_runtime.h>
#include <math.h>

#define NMAX 100000
#define EMAX 1000000
#define TOTMAX (EMAX + NMAX)

// ---------------- scratch (static device arrays; no allocation) ----------------
__device__ float4 g_h4[(size_t)NMAX * 32];        // h [N,128] as float4
__device__ float4 g_asrc4[NMAX];                  // a_src [N,4]
__device__ float4 g_adst4[NMAX];                  // a_dst [N,4]
__device__ float  g_amax[NMAX * 4];               // segment max [N,4]
__device__ float  g_denom[NMAX * 4];              // segment sum [N,4]
__device__ float4 g_alpha4[TOTMAX];               // per-edge logits [E+N,4]
__device__ int    g_is64;                         // edge_index dtype flag

// ---------------- helpers ----------------
__device__ __forceinline__ void atomicMaxF(float* addr, float v) {
    if (v >= 0.f) atomicMax((int*)addr, __float_as_int(v));
    else          atomicMin((unsigned int*)addr, __float_as_uint(v));
}

__device__ __forceinline__ int load_idx(const void* ei, long long i, int is64) {
    if (is64) return (int)((const long long*)ei)[i];
    return ((const int*)ei)[i];
}

// ---------------- dtype detection (int64 vs int32 edge_index) ----------------
__global__ void k_detect(const void* ei, int n) {
    const long long* p = (const long long*)ei;
    int ok = 1;
    for (int i = 0; i < 8; i++) {
        long long v = p[i];
        if (v < 0 || v >= n) ok = 0;
    }
    g_is64 = ok;
}

// ---------------- init: amax=-inf, denom=0 ----------------
__global__ void k_init(int n) {
    int i = blockIdx.x * blockDim.x + threadIdx.x;
    if (i < n * 4) { g_amax[i] = -INFINITY; g_denom[i] = 0.f; }
}

// ---------------- GEMM h = x@W fused with attention dots ----------------
// W (128x128 fp32 = 64KB) staged in dynamic smem. Warp computes 4 rows at a
// time (amortizes smem reads 4x). Packed f32x2 FMA halves FMA-pipe pressure.
__global__ void __launch_bounds__(256) k_gemm(
    const float* __restrict__ x, const float* __restrict__ W,
    const float* __restrict__ att_src, const float* __restrict__ att_dst, int n)
{
    extern __shared__ float sW[];
    {
        const float4* W4 = (const float4*)W;
        float4* s4 = (float4*)sW;
        for (int i = threadIdx.x; i < 128 * 32; i += 256) s4[i] = W4[i];
    }
    __syncthreads();

    const int lane = threadIdx.x & 31;
    const int wid = blockIdx.x * 8 + (threadIdx.x >> 5);
    const int nwarps = gridDim.x * 8;
    const float4 as4 = ((const float4*)att_src)[lane];
    const float4 ad4 = ((const float4*)att_dst)[lane];
    // smem row k: 128 floats = 32 x 16B; lane's 4 cols are ulonglong2 (2 f32x2)
    const ulonglong2* sWp = (const ulonglong2*)sW;

    for (int r0 = wid * 4; r0 < n; r0 += nwarps * 4) {
        float xr[4][4];
#pragma unroll
        for (int r = 0; r < 4; r++) {
            int row = min(r0 + r, n - 1);
            const float* xp = x + (size_t)row * 128;
            xr[r][0] = xp[lane];      xr[r][1] = xp[lane + 32];
            xr[r][2] = xp[lane + 64]; xr[r][3] = xp[lane + 96];
        }
        unsigned long long a0[4], a1[4];
#pragma unroll
        for (int r = 0; r < 4; r++) { a0[r] = 0ull; a1[r] = 0ull; }

#pragma unroll
        for (int j = 0; j < 4; j++) {
#pragma unroll
            for (int kk = 0; kk < 32; kk++) {
                ulonglong2 wv = sWp[(j * 32 + kk) * 32 + lane];
#pragma unroll
                for (int r = 0; r < 4; r++) {
                    float xk = __shfl_sync(0xffffffffu, xr[r][j], kk);
                    unsigned long long xp2;
                    asm("mov.b64 %0, {%1, %1};" : "=l"(xp2) : "f"(xk));
                    asm("fma.rn.f32x2 %0, %1, %2, %0;" : "+l"(a0[r]) : "l"(xp2), "l"(wv.x));
                    asm("fma.rn.f32x2 %0, %1, %2, %0;" : "+l"(a1[r]) : "l"(xp2), "l"(wv.y));
                }
            }
        }

#pragma unroll
        for (int r = 0; r < 4; r++) {
            int row = r0 + r;
            if (row < n) {
                float v0, v1, v2, v3;
                asm("mov.b64 {%0, %1}, %2;" : "=f"(v0), "=f"(v1) : "l"(a0[r]));
                asm("mov.b64 {%0, %1}, %2;" : "=f"(v2), "=f"(v3) : "l"(a1[r]));
                float4 h4 = make_float4(v0, v1, v2, v3);
                g_h4[(size_t)row * 32 + lane] = h4;
                float ps = h4.x * as4.x + h4.y * as4.y + h4.z * as4.z + h4.w * as4.w;
                float pd = h4.x * ad4.x + h4.y * ad4.y + h4.z * ad4.z + h4.w * ad4.w;
                // reduce within groups of 8 lanes (one head per group)
                ps += __shfl_xor_sync(0xffffffffu, ps, 4);
                pd += __shfl_xor_sync(0xffffffffu, pd, 4);
                ps += __shfl_xor_sync(0xffffffffu, ps, 2);
                pd += __shfl_xor_sync(0xffffffffu, pd, 2);
                ps += __shfl_xor_sync(0xffffffffu, ps, 1);
                pd += __shfl_xor_sync(0xffffffffu, pd, 1);
                if ((lane & 7) == 0) {
                    ((float*)g_asrc4)[row * 4 + (lane >> 3)] = ps;
                    ((float*)g_adst4)[row * 4 + (lane >> 3)] = pd;
                }
            }
        }
    }
}

// ---------------- edge pass 1: alpha + leaky relu + segment max ----------------
__global__ void k_alpha(const void* __restrict__ ei, int n, int E) {
    int e = blockIdx.x * blockDim.x + threadIdx.x;
    int tot = E + n;
    if (e >= tot) return;
    int is64 = g_is64;
    int src, dst;
    if (e < E) { src = load_idx(ei, e, is64); dst = load_idx(ei, (long long)E + e, is64); }
    else       { src = dst = e - E; }
    float4 s4 = g_asrc4[src];
    float4 d4 = g_adst4[dst];
    float4 al;
    al.x = s4.x + d4.x; al.x = al.x >= 0.f ? al.x : 0.2f * al.x;
    al.y = s4.y + d4.y; al.y = al.y >= 0.f ? al.y : 0.2f * al.y;
    al.z = s4.z + d4.z; al.z = al.z >= 0.f ? al.z : 0.2f * al.z;
    al.w = s4.w + d4.w; al.w = al.w >= 0.f ? al.w : 0.2f * al.w;
    g_alpha4[e] = al;
    atomicMaxF(&g_amax[dst * 4 + 0], al.x);
    atomicMaxF(&g_amax[dst * 4 + 1], al.y);
    atomicMaxF(&g_amax[dst * 4 + 2], al.z);
    atomicMaxF(&g_amax[dst * 4 + 3], al.w);
}

// ---------------- edge pass 2: exp, denom, fused weighted scatter ----------------
// One warp per edge. lane l covers output cols 4l..4l+3 (head = l>>3).
__global__ void __launch_bounds__(256) k_scatter(
    const void* __restrict__ ei, float* __restrict__ out, int n, int E)
{
    int w = (blockIdx.x * blockDim.x + threadIdx.x) >> 5;
    int lane = threadIdx.x & 31;
    int tot = E + n;
    if (w >= tot) return;
    int is64 = g_is64;
    int src, dst;
    if (w < E) { src = load_idx(ei, w, is64); dst = load_idx(ei, (long long)E + w, is64); }
    else       { src = dst = w - E; }
    int hh = lane >> 3;
    float al = ((const float*)g_alpha4)[(size_t)w * 4 + hh];
    float am = g_amax[dst * 4 + hh];
    float ex = __expf(al - am);
    if ((lane & 7) == 0) atomicAdd(&g_denom[dst * 4 + hh], ex);
    float4 hv = g_h4[(size_t)src * 32 + lane];
    float cx = hv.x * ex, cy = hv.y * ex, cz = hv.z * ex, cw = hv.w * ex;
    float* dp = out + (size_t)dst * 128 + lane * 4;
    asm volatile("red.global.add.v4.f32 [%0], {%1,%2,%3,%4};"
                 :: "l"(dp), "f"(cx), "f"(cy), "f"(cz), "f"(cw) : "memory");
}

// ---------------- normalize + bias ----------------
__global__ void k_norm(float* __restrict__ out, const float* __restrict__ bias, int n) {
    int t = blockIdx.x * blockDim.x + threadIdx.x;
    if (t >= n * 32) return;
    int node = t >> 5, j = t & 31;
    float den = g_denom[node * 4 + (j >> 3)];
    float inv = 1.f / (den + 1e-16f);
    float4 v = ((float4*)out)[(size_t)node * 32 + j];
    float4 b = ((const float4*)bias)[j];
    v.x = v.x * inv + b.x;
    v.y = v.y * inv + b.y;
    v.z = v.z * inv + b.z;
    v.w = v.w * inv + b.w;
    ((float4*)out)[(size_t)node * 32 + j] = v;
}

// ---------------- launch ----------------
extern "C" void kernel_launch(void* const* d_in, const int* in_sizes, int n_in,
                              void* d_out, int out_size)
{
    const float* x       = (const float*)d_in[0];
    const void*  ei      = d_in[1];
    const float* W       = (const float*)d_in[2];
    const float* att_src = (const float*)d_in[3];
    const float* att_dst = (const float*)d_in[4];
    const float* bias    = (const float*)d_in[5];
    float* out = (float*)d_out;

    int n = in_sizes[0] / 128;
    int E = in_sizes[1] / 2;
    int tot = E + n;

    cudaFuncSetAttribute(k_gemm, cudaFuncAttributeMaxDynamicSharedMemorySize, 65536);

    k_detect<<<1, 1>>>(ei, n);
    cudaMemsetAsync(d_out, 0, (size_t)out_size * sizeof(float));
    k_init<<<(n * 4 + 255) / 256, 256>>>(n);
    k_gemm<<<444, 256, 65536>>>(x, W, att_src, att_dst, n);
    k_alpha<<<(tot + 255) / 256, 256>>>(ei, n, E);
    {
        long long threads = (long long)tot * 32;
        int blocks = (int)((threads + 255) / 256);
        k_scatter<<<blocks, 256>>>(ei, out, n, E);
    }
    k_norm<<<(n * 32 + 255) / 256, 256>>>(out, bias, n);
}

// round 2
// speedup vs baseline: 1.5982x; 1.5982x over previous
#include <cuda_runtime.h>
#include <math.h>

#define NMAX 100000
#define EMAX 1000000

// ---------------- scratch (static device arrays; no allocation) ----------------
__device__ float4 g_h4[(size_t)NMAX * 32];        // h [N,128] as float4
__device__ float4 g_asrc4[NMAX];                  // a_src [N,4]
__device__ float4 g_adst4[NMAX];                  // a_dst [N,4]
__device__ int    g_cnt[NMAX];                    // in-degree counts
__device__ int    g_rowptr[NMAX + 1];             // CSR row pointers (by dst)
__device__ int    g_cur[NMAX];                    // fill cursors
__device__ int    g_part[256];                    // scan block partials
__device__ int    g_adj[EMAX];                    // adjacency: src ids grouped by dst
__device__ int    g_is64;                         // edge_index dtype flag

// ---------------- helpers ----------------
__device__ __forceinline__ int load_idx(const void* ei, long long i, int is64) {
    if (is64) return (int)((const long long*)ei)[i];
    return ((const int*)ei)[i];
}
__device__ __forceinline__ float lrelu(float v) { return v >= 0.f ? v : 0.2f * v; }

// ---------------- dtype detection (int64 vs int32 edge_index) ----------------
__global__ void k_detect(const void* ei, int n) {
    const long long* p = (const long long*)ei;
    int ok = 1;
    for (int i = 0; i < 8; i++) {
        long long v = p[i];
        if (v < 0 || v >= n) ok = 0;
    }
    g_is64 = ok;
}

__global__ void k_zero(int n) {
    int i = blockIdx.x * blockDim.x + threadIdx.x;
    if (i < n) g_cnt[i] = 0;
}

// ---------------- GEMM h = x@W fused with attention dots ----------------
__global__ void __launch_bounds__(256) k_gemm(
    const float* __restrict__ x, const float* __restrict__ W,
    const float* __restrict__ att_src, const float* __restrict__ att_dst, int n)
{
    extern __shared__ float sW[];
    {
        const float4* W4 = (const float4*)W;
        float4* s4 = (float4*)sW;
        for (int i = threadIdx.x; i < 128 * 32; i += 256) s4[i] = W4[i];
    }
    __syncthreads();

    const int lane = threadIdx.x & 31;
    const int wid = blockIdx.x * 8 + (threadIdx.x >> 5);
    const int nwarps = gridDim.x * 8;
    const float4 as4 = ((const float4*)att_src)[lane];
    const float4 ad4 = ((const float4*)att_dst)[lane];
    const ulonglong2* sWp = (const ulonglong2*)sW;

    for (int r0 = wid * 4; r0 < n; r0 += nwarps * 4) {
        float xr[4][4];
#pragma unroll
        for (int r = 0; r < 4; r++) {
            int row = min(r0 + r, n - 1);
            const float* xp = x + (size_t)row * 128;
            xr[r][0] = xp[lane];      xr[r][1] = xp[lane + 32];
            xr[r][2] = xp[lane + 64]; xr[r][3] = xp[lane + 96];
        }
        unsigned long long a0[4], a1[4];
#pragma unroll
        for (int r = 0; r < 4; r++) { a0[r] = 0ull; a1[r] = 0ull; }

#pragma unroll
        for (int j = 0; j < 4; j++) {
#pragma unroll
            for (int kk = 0; kk < 32; kk++) {
                ulonglong2 wv = sWp[(j * 32 + kk) * 32 + lane];
#pragma unroll
                for (int r = 0; r < 4; r++) {
                    float xk = __shfl_sync(0xffffffffu, xr[r][j], kk);
                    unsigned long long xp2;
                    asm("mov.b64 %0, {%1, %1};" : "=l"(xp2) : "f"(xk));
                    asm("fma.rn.f32x2 %0, %1, %2, %0;" : "+l"(a0[r]) : "l"(xp2), "l"(wv.x));
                    asm("fma.rn.f32x2 %0, %1, %2, %0;" : "+l"(a1[r]) : "l"(xp2), "l"(wv.y));
                }
            }
        }

#pragma unroll
        for (int r = 0; r < 4; r++) {
            int row = r0 + r;
            if (row < n) {
                float v0, v1, v2, v3;
                asm("mov.b64 {%0, %1}, %2;" : "=f"(v0), "=f"(v1) : "l"(a0[r]));
                asm("mov.b64 {%0, %1}, %2;" : "=f"(v2), "=f"(v3) : "l"(a1[r]));
                float4 h4 = make_float4(v0, v1, v2, v3);
                g_h4[(size_t)row * 32 + lane] = h4;
                float ps = h4.x * as4.x + h4.y * as4.y + h4.z * as4.z + h4.w * as4.w;
                float pd = h4.x * ad4.x + h4.y * ad4.y + h4.z * ad4.z + h4.w * ad4.w;
                ps += __shfl_xor_sync(0xffffffffu, ps, 4);
                pd += __shfl_xor_sync(0xffffffffu, pd, 4);
                ps += __shfl_xor_sync(0xffffffffu, ps, 2);
                pd += __shfl_xor_sync(0xffffffffu, pd, 2);
                ps += __shfl_xor_sync(0xffffffffu, ps, 1);
                pd += __shfl_xor_sync(0xffffffffu, pd, 1);
                if ((lane & 7) == 0) {
                    ((float*)g_asrc4)[row * 4 + (lane >> 3)] = ps;
                    ((float*)g_adst4)[row * 4 + (lane >> 3)] = pd;
                }
            }
        }
    }
}

// ---------------- CSR build: histogram ----------------
__global__ void k_hist(const void* __restrict__ ei, int E) {
    int e = blockIdx.x * blockDim.x + threadIdx.x;
    if (e >= E) return;
    int dst = load_idx(ei, (long long)E + e, g_is64);
    atomicAdd(&g_cnt[dst], 1);
}

// ---------------- CSR build: scan (3 phases) ----------------
#define SCAN_BLK 1024
__global__ void k_scan1(int n) {   // block partial sums
    __shared__ int sred[256];
    int b = blockIdx.x, t = threadIdx.x;
    int base = b * SCAN_BLK + t * 4;
    int s = 0;
#pragma unroll
    for (int u = 0; u < 4; u++) { int idx = base + u; if (idx < n) s += g_cnt[idx]; }
    sred[t] = s; __syncthreads();
    for (int off = 128; off > 0; off >>= 1) {
        if (t < off) sred[t] += sred[t + off];
        __syncthreads();
    }
    if (t == 0) g_part[b] = sred[0];
}
__global__ void k_scan2(int nb) {  // exclusive scan of partials (single block, 128 thr)
    __shared__ int sp[128];
    int t = threadIdx.x;
    int v = (t < nb) ? g_part[t] : 0;
    sp[t] = v; __syncthreads();
    for (int off = 1; off < 128; off <<= 1) {
        int u = (t >= off) ? sp[t - off] : 0;
        __syncthreads();
        sp[t] += u;
        __syncthreads();
    }
    if (t < nb) g_part[t] = sp[t] - v;  // exclusive
}
__global__ void k_scan3(int n, int E) {  // local scan + offsets -> rowptr, cur
    __shared__ int ssum[256];
    int b = blockIdx.x, t = threadIdx.x;
    int base = b * SCAN_BLK + t * 4;
    int c[4]; int s = 0;
#pragma unroll
    for (int u = 0; u < 4; u++) { int idx = base + u; c[u] = (idx < n) ? g_cnt[idx] : 0; s += c[u]; }
    ssum[t] = s; __syncthreads();
    for (int off = 1; off < 256; off <<= 1) {
        int u = (t >= off) ? ssum[t - off] : 0;
        __syncthreads();
        ssum[t] += u;
        __syncthreads();
    }
    int run = g_part[b] + ssum[t] - s;
#pragma unroll
    for (int u = 0; u < 4; u++) {
        int idx = base + u;
        if (idx < n) { g_rowptr[idx] = run; g_cur[idx] = run; run += c[u]; }
    }
    if (b == 0 && t == 0) g_rowptr[n] = E;
}

// ---------------- CSR build: fill ----------------
__global__ void k_fill(const void* __restrict__ ei, int E) {
    int e = blockIdx.x * blockDim.x + threadIdx.x;
    if (e >= E) return;
    int is64 = g_is64;
    int src = load_idx(ei, e, is64);
    int dst = load_idx(ei, (long long)E + e, is64);
    int pos = atomicAdd(&g_cur[dst], 1);
    g_adj[pos] = src;
}

// ---------------- fused gather: softmax + weighted aggregation + bias ----------------
// One warp per dst node. Lane l handles output cols 4l..4l+3 (head = l>>3).
__global__ void __launch_bounds__(256) k_gather(
    const float* __restrict__ bias, float* __restrict__ out, int n)
{
    __shared__ int   s_src[8][32];
    __shared__ float s_ex[8][32][4];
    const int lane = threadIdx.x & 31;
    const int wslot = threadIdx.x >> 5;
    const int i = (blockIdx.x * blockDim.x + threadIdx.x) >> 5;
    if (i >= n) return;
    const int hidx = lane >> 3;
    const unsigned FULL = 0xffffffffu;

    int start = g_rowptr[i];
    int deg = g_rowptr[i + 1] - start;
    float4 adst = g_adst4[i];
    float4 aself;
    {
        float4 as = g_asrc4[i];
        aself.x = lrelu(as.x + adst.x); aself.y = lrelu(as.y + adst.y);
        aself.z = lrelu(as.z + adst.z); aself.w = lrelu(as.w + adst.w);
    }

    // Phase A: segment max (self-loop alpha is a valid lower bound / member)
    float4 mx = aself;
    for (int e = lane; e < deg; e += 32) {
        int s = g_adj[start + e];
        float4 as = g_asrc4[s];
        mx.x = fmaxf(mx.x, lrelu(as.x + adst.x));
        mx.y = fmaxf(mx.y, lrelu(as.y + adst.y));
        mx.z = fmaxf(mx.z, lrelu(as.z + adst.z));
        mx.w = fmaxf(mx.w, lrelu(as.w + adst.w));
    }
#pragma unroll
    for (int off = 16; off > 0; off >>= 1) {
        mx.x = fmaxf(mx.x, __shfl_xor_sync(FULL, mx.x, off));
        mx.y = fmaxf(mx.y, __shfl_xor_sync(FULL, mx.y, off));
        mx.z = fmaxf(mx.z, __shfl_xor_sync(FULL, mx.z, off));
        mx.w = fmaxf(mx.w, __shfl_xor_sync(FULL, mx.w, off));
    }

    // Phase B: exp + denom + weighted accumulation
    float4 acc = make_float4(0.f, 0.f, 0.f, 0.f);
    float4 den = make_float4(0.f, 0.f, 0.f, 0.f);
    const float* exf = &s_ex[wslot][0][0];

    for (int base = 0; base < deg; base += 32) {
        int e = base + lane;
        int s = 0;
        float4 ex4 = make_float4(0.f, 0.f, 0.f, 0.f);
        if (e < deg) {
            s = g_adj[start + e];
            float4 as = g_asrc4[s];
            ex4.x = __expf(lrelu(as.x + adst.x) - mx.x);
            ex4.y = __expf(lrelu(as.y + adst.y) - mx.y);
            ex4.z = __expf(lrelu(as.z + adst.z) - mx.z);
            ex4.w = __expf(lrelu(as.w + adst.w) - mx.w);
            den.x += ex4.x; den.y += ex4.y; den.z += ex4.z; den.w += ex4.w;
        }
        s_src[wslot][lane] = s;
        s_ex[wslot][lane][0] = ex4.x; s_ex[wslot][lane][1] = ex4.y;
        s_ex[wslot][lane][2] = ex4.z; s_ex[wslot][lane][3] = ex4.w;
        __syncwarp();

        int cnt = min(32, deg - base);
        int j = 0;
        for (; j + 4 <= cnt; j += 4) {
            int s0 = s_src[wslot][j + 0], s1 = s_src[wslot][j + 1];
            int s2 = s_src[wslot][j + 2], s3 = s_src[wslot][j + 3];
            float w0 = exf[(j + 0) * 4 + hidx], w1 = exf[(j + 1) * 4 + hidx];
            float w2 = exf[(j + 2) * 4 + hidx], w3 = exf[(j + 3) * 4 + hidx];
            float4 h0 = g_h4[(size_t)s0 * 32 + lane];
            float4 h1 = g_h4[(size_t)s1 * 32 + lane];
            float4 h2 = g_h4[(size_t)s2 * 32 + lane];
            float4 h3 = g_h4[(size_t)s3 * 32 + lane];
            acc.x += w0 * h0.x; acc.y += w0 * h0.y; acc.z += w0 * h0.z; acc.w += w0 * h0.w;
            acc.x += w1 * h1.x; acc.y += w1 * h1.y; acc.z += w1 * h1.z; acc.w += w1 * h1.w;
            acc.x += w2 * h2.x; acc.y += w2 * h2.y; acc.z += w2 * h2.z; acc.w += w2 * h2.w;
            acc.x += w3 * h3.x; acc.y += w3 * h3.y; acc.z += w3 * h3.z; acc.w += w3 * h3.w;
        }
        for (; j < cnt; j++) {
            int sj = s_src[wslot][j];
            float w = exf[j * 4 + hidx];
            float4 hv = g_h4[(size_t)sj * 32 + lane];
            acc.x += w * hv.x; acc.y += w * hv.y; acc.z += w * hv.z; acc.w += w * hv.w;
        }
        __syncwarp();
    }

    // self-loop contribution
    float4 exs;
    exs.x = __expf(aself.x - mx.x); exs.y = __expf(aself.y - mx.y);
    exs.z = __expf(aself.z - mx.z); exs.w = __expf(aself.w - mx.w);
    {
        float ws = (hidx == 0) ? exs.x : (hidx == 1) ? exs.y : (hidx == 2) ? exs.z : exs.w;
        float4 hv = g_h4[(size_t)i * 32 + lane];
        acc.x += ws * hv.x; acc.y += ws * hv.y; acc.z += ws * hv.z; acc.w += ws * hv.w;
    }

    // reduce denom across warp, add self term
#pragma unroll
    for (int off = 16; off > 0; off >>= 1) {
        den.x += __shfl_xor_sync(FULL, den.x, off);
        den.y += __shfl_xor_sync(FULL, den.y, off);
        den.z += __shfl_xor_sync(FULL, den.z, off);
        den.w += __shfl_xor_sync(FULL, den.w, off);
    }
    den.x += exs.x; den.y += exs.y; den.z += exs.z; den.w += exs.w;

    float dh = (hidx == 0) ? den.x : (hidx == 1) ? den.y : (hidx == 2) ? den.z : den.w;
    float inv = 1.f / (dh + 1e-16f);
    float4 b4 = ((const float4*)bias)[lane];
    float4 o;
    o.x = acc.x * inv + b4.x; o.y = acc.y * inv + b4.y;
    o.z = acc.z * inv + b4.z; o.w = acc.w * inv + b4.w;
    ((float4*)out)[(size_t)i * 32 + lane] = o;
}

// ---------------- launch ----------------
extern "C" void kernel_launch(void* const* d_in, const int* in_sizes, int n_in,
                              void* d_out, int out_size)
{
    const float* x       = (const float*)d_in[0];
    const void*  ei      = d_in[1];
    const float* W       = (const float*)d_in[2];
    const float* att_src = (const float*)d_in[3];
    const float* att_dst = (const float*)d_in[4];
    const float* bias    = (const float*)d_in[5];
    float* out = (float*)d_out;

    int n = in_sizes[0] / 128;
    int E = in_sizes[1] / 2;
    int nb = (n + SCAN_BLK - 1) / SCAN_BLK;

    cudaFuncSetAttribute(k_gemm, cudaFuncAttributeMaxDynamicSharedMemorySize, 65536);

    k_detect<<<1, 1>>>(ei, n);
    k_zero<<<(n + 255) / 256, 256>>>(n);
    k_gemm<<<444, 256, 65536>>>(x, W, att_src, att_dst, n);
    k_hist<<<(E + 255) / 256, 256>>>(ei, E);
    k_scan1<<<nb, 256>>>(n);
    k_scan2<<<1, 128>>>(nb);
    k_scan3<<<nb, 256>>>(n, E);
    k_fill<<<(E + 255) / 256, 256>>>(ei, E);
    k_gather<<<(n + 7) / 8, 256>>>(bias, out, n);
}